// round 13
// baseline (speedup 1.0000x reference)
#include <cuda_runtime.h>
#include <cuda_bf16.h>
#include <cuda_fp16.h>
#include <cstdint>

#define MAX_N 100000
#define MAX_E 1600000
#define D 128
#define NB_MAX 128

// Scratch (device globals -- no allocation allowed)
__device__ __half g_hh[(size_t)MAX_N * D];     // 25.6 MB fp16 h
__device__ float g_si[MAX_N];
__device__ float g_sj[MAX_N];
__device__ int   g_cnt[MAX_N];                 // edge hist; countdown restores to 0
__device__ int   g_offp[MAX_N];                // block-local exclusive prefix
__device__ int   g_bsum[NB_MAX];
__device__ int   g_bpre[NB_MAX];
__device__ int   g_pos[MAX_E];                 // slot for edge t (coalesced)
__device__ uint2 g_de[MAX_E];                  // sorted packed (dst, exp(score))

__device__ __forceinline__ unsigned h2_to_u32(__half2 h) {
    unsigned u; *reinterpret_cast<__half2*>(&u) = h; return u;
}
__device__ __forceinline__ __half2 u32_to_h2(unsigned u) {
    return *reinterpret_cast<__half2*>(&u);
}

// ---------------------------------------------------------------------------
// Tensor-core GEMM: h = x @ W^T + b via mma.sync m16n8k16 f16f16f32.
// Block tile 128x128, K chunked 2x64. 8 warps: 4 in M x 2 in N.
// (round-7 proven configuration)
// ---------------------------------------------------------------------------
#define KC 64
#define XPITCH 72              // smem row pitch in halves (64 + 8 pad)
#define HPITCH 136             // epilogue pitch (128 + 8 pad)

__global__ __launch_bounds__(256, 2)
void gemm_kernel(const float* __restrict__ x, const float* __restrict__ W,
                 const float* __restrict__ b, const float* __restrict__ Watt,
                 int n) {
    __shared__ __align__(16) char smem_raw[2 * 128 * XPITCH * 2]; // 36864 B
    __half (*xs)[XPITCH] = (__half(*)[XPITCH])smem_raw;
    __half (*ws)[XPITCH] = (__half(*)[XPITCH])(smem_raw + 128 * XPITCH * 2);
    __half (*hs)[HPITCH] = (__half(*)[HPITCH])smem_raw;   // epilogue reuse

    int tid = threadIdx.x;
    int wid = tid >> 5;
    int lane = tid & 31;
    int gid = lane >> 2;
    int tig = lane & 3;
    int wm = wid & 3;
    int wn = wid >> 2;
    int row0 = blockIdx.x * 128;

    float c[2][8][4];
#pragma unroll
    for (int mi = 0; mi < 2; mi++)
#pragma unroll
        for (int ni = 0; ni < 8; ni++)
#pragma unroll
            for (int r = 0; r < 4; r++) c[mi][ni][r] = 0.f;

#pragma unroll
    for (int kk = 0; kk < D; kk += KC) {
#pragma unroll
        for (int r = 0; r < 8; r++) {
            int idx = tid + r * 256;
            int row = idx >> 4;
            int c4 = (idx & 15) * 4;
            float4 v = make_float4(0.f, 0.f, 0.f, 0.f);
            int gr = row0 + row;
            if (gr < n) v = *(const float4*)&x[(size_t)gr * D + kk + c4];
            unsigned p0 = h2_to_u32(__floats2half2_rn(v.x, v.y));
            unsigned p1 = h2_to_u32(__floats2half2_rn(v.z, v.w));
            *(uint2*)&xs[row][c4] = make_uint2(p0, p1);
        }
#pragma unroll
        for (int r = 0; r < 8; r++) {
            int idx = tid + r * 256;
            int cc = idx >> 4;
            int c4 = (idx & 15) * 4;
            float4 v = *(const float4*)&W[(size_t)cc * D + kk + c4];
            unsigned p0 = h2_to_u32(__floats2half2_rn(v.x, v.y));
            unsigned p1 = h2_to_u32(__floats2half2_rn(v.z, v.w));
            *(uint2*)&ws[cc][c4] = make_uint2(p0, p1);
        }
        __syncthreads();

#pragma unroll
        for (int ks = 0; ks < KC / 16; ks++) {
            int kb = ks * 16 + tig * 2;
            unsigned a[2][4];
#pragma unroll
            for (int mi = 0; mi < 2; mi++) {
                int ra = wm * 32 + mi * 16 + gid;
                a[mi][0] = *(const unsigned*)&xs[ra][kb];
                a[mi][1] = *(const unsigned*)&xs[ra + 8][kb];
                a[mi][2] = *(const unsigned*)&xs[ra][kb + 8];
                a[mi][3] = *(const unsigned*)&xs[ra + 8][kb + 8];
            }
#pragma unroll
            for (int ni = 0; ni < 8; ni++) {
                int cb = wn * 64 + ni * 8 + gid;
                unsigned b0 = *(const unsigned*)&ws[cb][kb];
                unsigned b1 = *(const unsigned*)&ws[cb][kb + 8];
#pragma unroll
                for (int mi = 0; mi < 2; mi++) {
                    asm volatile(
                        "mma.sync.aligned.m16n8k16.row.col.f32.f16.f16.f32 "
                        "{%0,%1,%2,%3}, {%4,%5,%6,%7}, {%8,%9}, {%0,%1,%2,%3};"
                        : "+f"(c[mi][ni][0]), "+f"(c[mi][ni][1]),
                          "+f"(c[mi][ni][2]), "+f"(c[mi][ni][3])
                        : "r"(a[mi][0]), "r"(a[mi][1]), "r"(a[mi][2]), "r"(a[mi][3]),
                          "r"(b0), "r"(b1));
                }
            }
        }
        __syncthreads();
    }

    // epilogue pass 1: +bias, fp16, stage in smem
#pragma unroll
    for (int mi = 0; mi < 2; mi++) {
#pragma unroll
        for (int ni = 0; ni < 8; ni++) {
            int rr = wm * 32 + mi * 16 + gid;
            int col = wn * 64 + ni * 8 + tig * 2;
            float bx = __ldg(&b[col]);
            float by = __ldg(&b[col + 1]);
            *(unsigned*)&hs[rr][col] =
                h2_to_u32(__floats2half2_rn(c[mi][ni][0] + bx, c[mi][ni][1] + by));
            *(unsigned*)&hs[rr + 8][col] =
                h2_to_u32(__floats2half2_rn(c[mi][ni][2] + bx, c[mi][ni][3] + by));
        }
    }
    __syncthreads();

    // epilogue pass 2: coalesced store + fused s_i/s_j
    int tx = tid & 15;
    int tyr = tid >> 4;
    float ai_r[8], aj_r[8];
#pragma unroll
    for (int j = 0; j < 8; j++) {
        ai_r[j] = __ldg(&Watt[tx * 8 + j]);
        aj_r[j] = __ldg(&Watt[D + tx * 8 + j]);
    }
#pragma unroll
    for (int it = 0; it < 8; it++) {
        int row = it * 16 + tyr;
        int gr = row0 + row;
        uint4 v = *(const uint4*)&hs[row][tx * 8];
        float2 f0 = __half22float2(u32_to_h2(v.x));
        float2 f1 = __half22float2(u32_to_h2(v.y));
        float2 f2 = __half22float2(u32_to_h2(v.z));
        float2 f3 = __half22float2(u32_to_h2(v.w));
        float psi = f0.x*ai_r[0] + f0.y*ai_r[1] + f1.x*ai_r[2] + f1.y*ai_r[3]
                  + f2.x*ai_r[4] + f2.y*ai_r[5] + f3.x*ai_r[6] + f3.y*ai_r[7];
        float psj = f0.x*aj_r[0] + f0.y*aj_r[1] + f1.x*aj_r[2] + f1.y*aj_r[3]
                  + f2.x*aj_r[4] + f2.y*aj_r[5] + f3.x*aj_r[6] + f3.y*aj_r[7];
#pragma unroll
        for (int o = 8; o; o >>= 1) {
            psi += __shfl_down_sync(0xffffffffu, psi, o, 16);
            psj += __shfl_down_sync(0xffffffffu, psj, o, 16);
        }
        if (gr < n) {
            *(uint4*)&g_hh[(size_t)gr * D + tx * 8] = v;
            if (tx == 0) { g_si[gr] = psi; g_sj[gr] = psj; }
        }
    }
}

// ---------------------------------------------------------------------------
// hist: 4 edges per thread
// ---------------------------------------------------------------------------
__global__ void hist_kernel(const int* __restrict__ ei, int E) {
    int t4 = (blockIdx.x * blockDim.x + threadIdx.x) * 4;
    if (t4 + 3 < E) {
        int4 s4 = *(const int4*)&ei[t4];
        atomicAdd(&g_cnt[s4.x], 1);
        atomicAdd(&g_cnt[s4.y], 1);
        atomicAdd(&g_cnt[s4.z], 1);
        atomicAdd(&g_cnt[s4.w], 1);
    } else {
        for (int t = t4; t < E; t++) atomicAdd(&g_cnt[ei[t]], 1);
    }
}

// ---------------------------------------------------------------------------
// exclusive scan over edge counts (self-loops NOT included in slots)
// ---------------------------------------------------------------------------
__global__ void scan1_kernel(int n) {
    __shared__ int sh[1024];
    int i = blockIdx.x * 1024 + threadIdx.x;
    int v = (i < n) ? g_cnt[i] : 0;
    sh[threadIdx.x] = v;
    __syncthreads();
    for (int off = 1; off < 1024; off <<= 1) {
        int t = (threadIdx.x >= off) ? sh[threadIdx.x - off] : 0;
        __syncthreads();
        sh[threadIdx.x] += t;
        __syncthreads();
    }
    if (i < n) g_offp[i] = sh[threadIdx.x] - v;
    if (threadIdx.x == 1023) g_bsum[blockIdx.x] = sh[1023];
}

__global__ void scan2_kernel(int nb) {
    __shared__ int sh[NB_MAX];
    int t = threadIdx.x;
    int v = (t < nb) ? g_bsum[t] : 0;
    sh[t] = v;
    __syncthreads();
    for (int off = 1; off < NB_MAX; off <<= 1) {
        int u = (t >= off) ? sh[t - off] : 0;
        __syncthreads();
        sh[t] += u;
        __syncthreads();
    }
    if (t < nb) g_bpre[t] = sh[t] - v;
}

// ---------------------------------------------------------------------------
// slot: per-edge countdown atomic -> slot index, written COALESCED to g_pos.
// No scattered writes; runs concurrent with GEMM. g_cnt ends at 0.
// ---------------------------------------------------------------------------
__global__ void slot_kernel(const int* __restrict__ ei, int E) {
    int t4 = (blockIdx.x * blockDim.x + threadIdx.x) * 4;
    if (t4 + 3 < E) {
        int4 s4 = *(const int4*)&ei[t4];
        int4 p;
        p.x = g_offp[s4.x] + g_bpre[s4.x >> 10] + atomicAdd(&g_cnt[s4.x], -1) - 1;
        p.y = g_offp[s4.y] + g_bpre[s4.y >> 10] + atomicAdd(&g_cnt[s4.y], -1) - 1;
        p.z = g_offp[s4.z] + g_bpre[s4.z >> 10] + atomicAdd(&g_cnt[s4.z], -1) - 1;
        p.w = g_offp[s4.w] + g_bpre[s4.w >> 10] + atomicAdd(&g_cnt[s4.w], -1) - 1;
        *(int4*)&g_pos[t4] = p;
    } else {
        for (int t = t4; t < E; t++) {
            int src = ei[t];
            g_pos[t] = g_offp[src] + g_bpre[src >> 10]
                     + atomicAdd(&g_cnt[src], -1) - 1;
        }
    }
}

// ---------------------------------------------------------------------------
// score: compute e = exp(lrelu(si[src]+sj[dst]+b)), write packed (dst, e)
// record to its precomputed slot. Atomic-free; only scatter is the 8B store.
// ---------------------------------------------------------------------------
__global__ void score_kernel(const int* __restrict__ ei,
                             const float* __restrict__ batt, int E) {
    int t = blockIdx.x * blockDim.x + threadIdx.x;
    if (t >= E) return;
    int src = ei[t];
    int dst = ei[E + t];
    float sc = g_si[src] + g_sj[dst] + __ldg(batt);
    sc = (sc >= 0.f) ? sc : 0.01f * sc;
    float e = expf(sc);
    g_de[g_pos[t]] = make_uint2((unsigned)dst, __float_as_uint(e));
}

// ---------------------------------------------------------------------------
// aggregation (round-10 proven form): warp per src node, packed uint2
// records, 4-wide unroll, fp16 row gathers (8B/lane), fp32 accumulate.
// Self-loop handled analytically. Fused normalize + ELU.
// ---------------------------------------------------------------------------
__global__ __launch_bounds__(256)
void aggregate_kernel(float* __restrict__ out, const float* __restrict__ batt,
                      int n, int E) {
    int w = (blockIdx.x * blockDim.x + threadIdx.x) >> 5;
    int lane = threadIdx.x & 31;
    if (w >= n) return;
    int s = g_offp[w] + g_bpre[w >> 10];
    int e = (w + 1 < n) ? (g_offp[w + 1] + g_bpre[(w + 1) >> 10]) : E;

    // self-loop term
    float scs = g_si[w] + g_sj[w] + __ldg(batt);
    scs = (scs >= 0.f) ? scs : 0.01f * scs;
    float es = expf(scs);

    float4 acc;
    {
        uint2 rw = *(const uint2*)&g_hh[(size_t)w * D + lane * 4];
        float2 a0 = __half22float2(u32_to_h2(rw.x));
        float2 a1 = __half22float2(u32_to_h2(rw.y));
        acc = make_float4(es * a0.x, es * a0.y, es * a1.x, es * a1.y);
    }
    float den = es;

    int k = s;
    for (; k + 3 < e; k += 4) {
        uint2 de0 = g_de[k],     de1 = g_de[k + 1];
        uint2 de2 = g_de[k + 2], de3 = g_de[k + 3];
        uint2 r0 = *(const uint2*)&g_hh[(size_t)de0.x * D + lane * 4];
        uint2 r1 = *(const uint2*)&g_hh[(size_t)de1.x * D + lane * 4];
        uint2 r2 = *(const uint2*)&g_hh[(size_t)de2.x * D + lane * 4];
        uint2 r3 = *(const uint2*)&g_hh[(size_t)de3.x * D + lane * 4];
        float e0 = __uint_as_float(de0.y), e1 = __uint_as_float(de1.y);
        float e2 = __uint_as_float(de2.y), e3 = __uint_as_float(de3.y);
        float2 a0 = __half22float2(u32_to_h2(r0.x));
        float2 a1 = __half22float2(u32_to_h2(r0.y));
        acc.x += e0 * a0.x; acc.y += e0 * a0.y; acc.z += e0 * a1.x; acc.w += e0 * a1.y;
        a0 = __half22float2(u32_to_h2(r1.x));
        a1 = __half22float2(u32_to_h2(r1.y));
        acc.x += e1 * a0.x; acc.y += e1 * a0.y; acc.z += e1 * a1.x; acc.w += e1 * a1.y;
        a0 = __half22float2(u32_to_h2(r2.x));
        a1 = __half22float2(u32_to_h2(r2.y));
        acc.x += e2 * a0.x; acc.y += e2 * a0.y; acc.z += e2 * a1.x; acc.w += e2 * a1.y;
        a0 = __half22float2(u32_to_h2(r3.x));
        a1 = __half22float2(u32_to_h2(r3.y));
        acc.x += e3 * a0.x; acc.y += e3 * a0.y; acc.z += e3 * a1.x; acc.w += e3 * a1.y;
        den += (e0 + e1) + (e2 + e3);
    }
    for (; k < e; k++) {
        uint2 de0 = g_de[k];
        uint2 r0 = *(const uint2*)&g_hh[(size_t)de0.x * D + lane * 4];
        float e0 = __uint_as_float(de0.y);
        float2 a0 = __half22float2(u32_to_h2(r0.x));
        float2 a1 = __half22float2(u32_to_h2(r0.y));
        acc.x += e0 * a0.x; acc.y += e0 * a0.y; acc.z += e0 * a1.x; acc.w += e0 * a1.y;
        den += e0;
    }

    float inv = 1.f / den;
    float4 o;
    o.x = acc.x * inv; o.y = acc.y * inv; o.z = acc.z * inv; o.w = acc.w * inv;
    o.x = (o.x > 0.f) ? o.x : expm1f(o.x);
    o.y = (o.y > 0.f) ? o.y : expm1f(o.y);
    o.z = (o.z > 0.f) ? o.z : expm1f(o.z);
    o.w = (o.w > 0.f) ? o.w : expm1f(o.w);
    float* p = &out[(size_t)w * D + lane * 4];
    asm volatile("st.global.cs.v4.f32 [%0], {%1,%2,%3,%4};"
                 :: "l"(p), "f"(o.x), "f"(o.y), "f"(o.z), "f"(o.w) : "memory");
}

// ---------------------------------------------------------------------------
extern "C" void kernel_launch(void* const* d_in, const int* in_sizes, int n_in,
                              void* d_out, int out_size) {
    const float* x    = (const float*)d_in[0];
    const int*   ei   = (const int*)  d_in[1];
    const float* W    = (const float*)d_in[2];
    const float* b    = (const float*)d_in[3];
    const float* Watt = (const float*)d_in[4];
    const float* batt = (const float*)d_in[5];
    float* out = (float*)d_out;

    int n = in_sizes[0] / D;
    int E = in_sizes[1] / 2;
    int nb = (n + 1023) / 1024;
    int e4 = (E + 3) / 4;

    // side stream + events for fork/join inside graph capture (created once)
    static cudaStream_t s1 = nullptr;
    static cudaEvent_t ev_fork = nullptr, ev_join = nullptr;
    if (s1 == nullptr) {
        cudaStreamCreateWithFlags(&s1, cudaStreamNonBlocking);
        cudaEventCreateWithFlags(&ev_fork, cudaEventDisableTiming);
        cudaEventCreateWithFlags(&ev_join, cudaEventDisableTiming);
    }

    // fork: score-free slot pipeline (hist -> scans -> slots), hidden by GEMM
    cudaEventRecord(ev_fork, 0);
    cudaStreamWaitEvent(s1, ev_fork, 0);
    hist_kernel<<<(e4 + 255) / 256, 256, 0, s1>>>(ei, E);
    scan1_kernel<<<nb, 1024, 0, s1>>>(n);
    scan2_kernel<<<1, NB_MAX, 0, s1>>>(nb);
    slot_kernel<<<(e4 + 255) / 256, 256, 0, s1>>>(ei, E);
    cudaEventRecord(ev_join, s1);

    gemm_kernel<<<(n + 127) / 128, 256>>>(x, W, b, Watt, n);

    cudaStreamWaitEvent(0, ev_join, 0);
    score_kernel<<<(E + 255) / 256, 256>>>(ei, batt, E);
    aggregate_kernel<<<((long long)n * 32 + 255) / 256, 256>>>(out, batt, n, E);
}

// round 14
// speedup vs baseline: 1.1347x; 1.1347x over previous
#include <cuda_runtime.h>
#include <cuda_bf16.h>
#include <cuda_fp16.h>
#include <cstdint>

#define MAX_N 100000
#define MAX_E 1600000
#define D 128
#define NB_MAX 128

// Scratch (device globals -- no allocation allowed)
__device__ __half g_hh[(size_t)MAX_N * D];     // 25.6 MB fp16 h
__device__ float g_si[MAX_N];
__device__ float g_sj[MAX_N];
__device__ int   g_cnt[MAX_N];                 // edge hist; countdown restores to 0
__device__ int   g_offp[MAX_N];                // block-local exclusive prefix
__device__ int   g_bsum[NB_MAX];
__device__ int   g_bpre[NB_MAX];
__device__ int   g_d[MAX_E];                   // dst sorted by src (edges only)

__device__ __forceinline__ unsigned h2_to_u32(__half2 h) {
    unsigned u; *reinterpret_cast<__half2*>(&u) = h; return u;
}
__device__ __forceinline__ __half2 u32_to_h2(unsigned u) {
    return *reinterpret_cast<__half2*>(&u);
}

// ---------------------------------------------------------------------------
// Tensor-core GEMM: h = x @ W^T + b via mma.sync m16n8k16 f16f16f32.
// Block tile 128x128, K chunked 2x64. 8 warps: 4 in M x 2 in N.
// (round-7 proven configuration)
// ---------------------------------------------------------------------------
#define KC 64
#define XPITCH 72              // smem row pitch in halves (64 + 8 pad)
#define HPITCH 136             // epilogue pitch (128 + 8 pad)

__global__ __launch_bounds__(256, 2)
void gemm_kernel(const float* __restrict__ x, const float* __restrict__ W,
                 const float* __restrict__ b, const float* __restrict__ Watt,
                 int n) {
    __shared__ __align__(16) char smem_raw[2 * 128 * XPITCH * 2]; // 36864 B
    __half (*xs)[XPITCH] = (__half(*)[XPITCH])smem_raw;
    __half (*ws)[XPITCH] = (__half(*)[XPITCH])(smem_raw + 128 * XPITCH * 2);
    __half (*hs)[HPITCH] = (__half(*)[HPITCH])smem_raw;   // epilogue reuse

    int tid = threadIdx.x;
    int wid = tid >> 5;
    int lane = tid & 31;
    int gid = lane >> 2;
    int tig = lane & 3;
    int wm = wid & 3;
    int wn = wid >> 2;
    int row0 = blockIdx.x * 128;

    float c[2][8][4];
#pragma unroll
    for (int mi = 0; mi < 2; mi++)
#pragma unroll
        for (int ni = 0; ni < 8; ni++)
#pragma unroll
            for (int r = 0; r < 4; r++) c[mi][ni][r] = 0.f;

#pragma unroll
    for (int kk = 0; kk < D; kk += KC) {
#pragma unroll
        for (int r = 0; r < 8; r++) {
            int idx = tid + r * 256;
            int row = idx >> 4;
            int c4 = (idx & 15) * 4;
            float4 v = make_float4(0.f, 0.f, 0.f, 0.f);
            int gr = row0 + row;
            if (gr < n) v = *(const float4*)&x[(size_t)gr * D + kk + c4];
            unsigned p0 = h2_to_u32(__floats2half2_rn(v.x, v.y));
            unsigned p1 = h2_to_u32(__floats2half2_rn(v.z, v.w));
            *(uint2*)&xs[row][c4] = make_uint2(p0, p1);
        }
#pragma unroll
        for (int r = 0; r < 8; r++) {
            int idx = tid + r * 256;
            int cc = idx >> 4;
            int c4 = (idx & 15) * 4;
            float4 v = *(const float4*)&W[(size_t)cc * D + kk + c4];
            unsigned p0 = h2_to_u32(__floats2half2_rn(v.x, v.y));
            unsigned p1 = h2_to_u32(__floats2half2_rn(v.z, v.w));
            *(uint2*)&ws[cc][c4] = make_uint2(p0, p1);
        }
        __syncthreads();

#pragma unroll
        for (int ks = 0; ks < KC / 16; ks++) {
            int kb = ks * 16 + tig * 2;
            unsigned a[2][4];
#pragma unroll
            for (int mi = 0; mi < 2; mi++) {
                int ra = wm * 32 + mi * 16 + gid;
                a[mi][0] = *(const unsigned*)&xs[ra][kb];
                a[mi][1] = *(const unsigned*)&xs[ra + 8][kb];
                a[mi][2] = *(const unsigned*)&xs[ra][kb + 8];
                a[mi][3] = *(const unsigned*)&xs[ra + 8][kb + 8];
            }
#pragma unroll
            for (int ni = 0; ni < 8; ni++) {
                int cb = wn * 64 + ni * 8 + gid;
                unsigned b0 = *(const unsigned*)&ws[cb][kb];
                unsigned b1 = *(const unsigned*)&ws[cb][kb + 8];
#pragma unroll
                for (int mi = 0; mi < 2; mi++) {
                    asm volatile(
                        "mma.sync.aligned.m16n8k16.row.col.f32.f16.f16.f32 "
                        "{%0,%1,%2,%3}, {%4,%5,%6,%7}, {%8,%9}, {%0,%1,%2,%3};"
                        : "+f"(c[mi][ni][0]), "+f"(c[mi][ni][1]),
                          "+f"(c[mi][ni][2]), "+f"(c[mi][ni][3])
                        : "r"(a[mi][0]), "r"(a[mi][1]), "r"(a[mi][2]), "r"(a[mi][3]),
                          "r"(b0), "r"(b1));
                }
            }
        }
        __syncthreads();
    }

    // epilogue pass 1: +bias, fp16, stage in smem
#pragma unroll
    for (int mi = 0; mi < 2; mi++) {
#pragma unroll
        for (int ni = 0; ni < 8; ni++) {
            int rr = wm * 32 + mi * 16 + gid;
            int col = wn * 64 + ni * 8 + tig * 2;
            float bx = __ldg(&b[col]);
            float by = __ldg(&b[col + 1]);
            *(unsigned*)&hs[rr][col] =
                h2_to_u32(__floats2half2_rn(c[mi][ni][0] + bx, c[mi][ni][1] + by));
            *(unsigned*)&hs[rr + 8][col] =
                h2_to_u32(__floats2half2_rn(c[mi][ni][2] + bx, c[mi][ni][3] + by));
        }
    }
    __syncthreads();

    // epilogue pass 2: coalesced store + fused s_i/s_j
    int tx = tid & 15;
    int tyr = tid >> 4;
    float ai_r[8], aj_r[8];
#pragma unroll
    for (int j = 0; j < 8; j++) {
        ai_r[j] = __ldg(&Watt[tx * 8 + j]);
        aj_r[j] = __ldg(&Watt[D + tx * 8 + j]);
    }
#pragma unroll
    for (int it = 0; it < 8; it++) {
        int row = it * 16 + tyr;
        int gr = row0 + row;
        uint4 v = *(const uint4*)&hs[row][tx * 8];
        float2 f0 = __half22float2(u32_to_h2(v.x));
        float2 f1 = __half22float2(u32_to_h2(v.y));
        float2 f2 = __half22float2(u32_to_h2(v.z));
        float2 f3 = __half22float2(u32_to_h2(v.w));
        float psi = f0.x*ai_r[0] + f0.y*ai_r[1] + f1.x*ai_r[2] + f1.y*ai_r[3]
                  + f2.x*ai_r[4] + f2.y*ai_r[5] + f3.x*ai_r[6] + f3.y*ai_r[7];
        float psj = f0.x*aj_r[0] + f0.y*aj_r[1] + f1.x*aj_r[2] + f1.y*aj_r[3]
                  + f2.x*aj_r[4] + f2.y*aj_r[5] + f3.x*aj_r[6] + f3.y*aj_r[7];
#pragma unroll
        for (int o = 8; o; o >>= 1) {
            psi += __shfl_down_sync(0xffffffffu, psi, o, 16);
            psj += __shfl_down_sync(0xffffffffu, psj, o, 16);
        }
        if (gr < n) {
            *(uint4*)&g_hh[(size_t)gr * D + tx * 8] = v;
            if (tx == 0) { g_si[gr] = psi; g_sj[gr] = psj; }
        }
    }
}

// ---------------------------------------------------------------------------
// hist: 4 edges per thread (ILP)
// ---------------------------------------------------------------------------
__global__ void hist_kernel(const int* __restrict__ ei, int E) {
    int t4 = (blockIdx.x * blockDim.x + threadIdx.x) * 4;
    if (t4 + 3 < E) {
        int4 s4 = *(const int4*)&ei[t4];
        atomicAdd(&g_cnt[s4.x], 1);
        atomicAdd(&g_cnt[s4.y], 1);
        atomicAdd(&g_cnt[s4.z], 1);
        atomicAdd(&g_cnt[s4.w], 1);
    } else {
        for (int t = t4; t < E; t++) atomicAdd(&g_cnt[ei[t]], 1);
    }
}

// ---------------------------------------------------------------------------
// exclusive scan over edge counts (self-loops NOT included in slots)
// ---------------------------------------------------------------------------
__global__ void scan1_kernel(int n) {
    __shared__ int sh[1024];
    int i = blockIdx.x * 1024 + threadIdx.x;
    int v = (i < n) ? g_cnt[i] : 0;
    sh[threadIdx.x] = v;
    __syncthreads();
    for (int off = 1; off < 1024; off <<= 1) {
        int t = (threadIdx.x >= off) ? sh[threadIdx.x - off] : 0;
        __syncthreads();
        sh[threadIdx.x] += t;
        __syncthreads();
    }
    if (i < n) g_offp[i] = sh[threadIdx.x] - v;
    if (threadIdx.x == 1023) g_bsum[blockIdx.x] = sh[1023];
}

__global__ void scan2_kernel(int nb) {
    __shared__ int sh[NB_MAX];
    int t = threadIdx.x;
    int v = (t < nb) ? g_bsum[t] : 0;
    sh[t] = v;
    __syncthreads();
    for (int off = 1; off < NB_MAX; off <<= 1) {
        int u = (t >= off) ? sh[t - off] : 0;
        __syncthreads();
        sh[t] += u;
        __syncthreads();
    }
    if (t < nb) g_bpre[t] = sh[t] - v;
}

// ---------------------------------------------------------------------------
// sort: counting-sort scatter of dst by src (score-free -> overlaps GEMM).
// g_cnt counts down to 0 (replay-safe).
// ---------------------------------------------------------------------------
__global__ void sort_kernel(const int* __restrict__ ei, int E) {
    int t = blockIdx.x * blockDim.x + threadIdx.x;
    if (t >= E) return;
    int src = ei[t];
    int dst = ei[E + t];
    int old = atomicAdd(&g_cnt[src], -1);
    g_d[g_offp[src] + g_bpre[src >> 10] + old - 1] = dst;
}

// ---------------------------------------------------------------------------
// aggregation: warp per src node, inline scoring with SMEM staging:
// phase A (lane-parallel): d_k, e_k = exp(lrelu(si[w]+sj[d_k]+b)) for up to
// 32 edges, stored to the warp's 256B smem row. phase B: broadcast LDS.128
// (2 pairs per load, conflict-free) feeds a 4-wide unrolled row gather --
// no per-edge shuffles on the critical path. Fused normalize + ELU.
// ---------------------------------------------------------------------------
__global__ __launch_bounds__(256)
void aggregate_kernel(float* __restrict__ out, const float* __restrict__ batt,
                      int n, int E) {
    __shared__ __align__(16) uint2 sde[8][32];   // per-warp staging (2 KB)
    int wl = threadIdx.x >> 5;                   // warp within block
    int w = (blockIdx.x * blockDim.x + threadIdx.x) >> 5;
    int lane = threadIdx.x & 31;
    if (w >= n) return;
    int s = g_offp[w] + g_bpre[w >> 10];
    int e = (w + 1 < n) ? (g_offp[w + 1] + g_bpre[(w + 1) >> 10]) : E;

    float bb = __ldg(batt);
    float si_w = g_si[w];

    // self-loop term
    float scs = si_w + g_sj[w] + bb;
    scs = (scs >= 0.f) ? scs : 0.01f * scs;
    float es = expf(scs);

    float4 acc;
    {
        uint2 rw = *(const uint2*)&g_hh[(size_t)w * D + lane * 4];
        float2 a0 = __half22float2(u32_to_h2(rw.x));
        float2 a1 = __half22float2(u32_to_h2(rw.y));
        acc = make_float4(es * a0.x, es * a0.y, es * a1.x, es * a1.y);
    }
    float denp = 0.f;   // per-lane partials (edges)

    for (int cs = s; cs < e; cs += 32) {
        int m = e - cs; if (m > 32) m = 32;
        // phase A: lane-parallel scoring
        uint2 p = make_uint2(0u, 0u);
        if (lane < m) {
            int dk = g_d[cs + lane];
            float sc = si_w + __ldg(&g_sj[dk]) + bb;
            sc = (sc >= 0.f) ? sc : 0.01f * sc;
            float ek = expf(sc);
            denp += ek;
            p = make_uint2((unsigned)dk, __float_as_uint(ek));
        }
        sde[wl][lane] = p;
        __syncwarp();
        // phase B: broadcast LDS.128 (2 pairs) + 4-wide gather
        int j = 0;
        for (; j + 3 < m; j += 4) {
            uint4 q01 = *(const uint4*)&sde[wl][j];       // pairs j, j+1
            uint4 q23 = *(const uint4*)&sde[wl][j + 2];   // pairs j+2, j+3
            uint2 r0 = *(const uint2*)&g_hh[(size_t)q01.x * D + lane * 4];
            uint2 r1 = *(const uint2*)&g_hh[(size_t)q01.z * D + lane * 4];
            uint2 r2 = *(const uint2*)&g_hh[(size_t)q23.x * D + lane * 4];
            uint2 r3 = *(const uint2*)&g_hh[(size_t)q23.z * D + lane * 4];
            float e0 = __uint_as_float(q01.y), e1 = __uint_as_float(q01.w);
            float e2 = __uint_as_float(q23.y), e3 = __uint_as_float(q23.w);
            float2 a0 = __half22float2(u32_to_h2(r0.x));
            float2 a1 = __half22float2(u32_to_h2(r0.y));
            acc.x += e0 * a0.x; acc.y += e0 * a0.y; acc.z += e0 * a1.x; acc.w += e0 * a1.y;
            a0 = __half22float2(u32_to_h2(r1.x));
            a1 = __half22float2(u32_to_h2(r1.y));
            acc.x += e1 * a0.x; acc.y += e1 * a0.y; acc.z += e1 * a1.x; acc.w += e1 * a1.y;
            a0 = __half22float2(u32_to_h2(r2.x));
            a1 = __half22float2(u32_to_h2(r2.y));
            acc.x += e2 * a0.x; acc.y += e2 * a0.y; acc.z += e2 * a1.x; acc.w += e2 * a1.y;
            a0 = __half22float2(u32_to_h2(r3.x));
            a1 = __half22float2(u32_to_h2(r3.y));
            acc.x += e3 * a0.x; acc.y += e3 * a0.y; acc.z += e3 * a1.x; acc.w += e3 * a1.y;
        }
        for (; j < m; j++) {
            uint2 q = sde[wl][j];
            uint2 r0 = *(const uint2*)&g_hh[(size_t)q.x * D + lane * 4];
            float e0 = __uint_as_float(q.y);
            float2 a0 = __half22float2(u32_to_h2(r0.x));
            float2 a1 = __half22float2(u32_to_h2(r0.y));
            acc.x += e0 * a0.x; acc.y += e0 * a0.y; acc.z += e0 * a1.x; acc.w += e0 * a1.y;
        }
        __syncwarp();
    }

    // reduce den across lanes, add self-loop term
    float den = denp;
#pragma unroll
    for (int o = 16; o; o >>= 1) den += __shfl_xor_sync(0xffffffffu, den, o);
    den += es;

    float inv = 1.f / den;
    float4 o;
    o.x = acc.x * inv; o.y = acc.y * inv; o.z = acc.z * inv; o.w = acc.w * inv;
    o.x = (o.x > 0.f) ? o.x : expm1f(o.x);
    o.y = (o.y > 0.f) ? o.y : expm1f(o.y);
    o.z = (o.z > 0.f) ? o.z : expm1f(o.z);
    o.w = (o.w > 0.f) ? o.w : expm1f(o.w);
    float* p = &out[(size_t)w * D + lane * 4];
    asm volatile("st.global.cs.v4.f32 [%0], {%1,%2,%3,%4};"
                 :: "l"(p), "f"(o.x), "f"(o.y), "f"(o.z), "f"(o.w) : "memory");
}

// ---------------------------------------------------------------------------
extern "C" void kernel_launch(void* const* d_in, const int* in_sizes, int n_in,
                              void* d_out, int out_size) {
    const float* x    = (const float*)d_in[0];
    const int*   ei   = (const int*)  d_in[1];
    const float* W    = (const float*)d_in[2];
    const float* b    = (const float*)d_in[3];
    const float* Watt = (const float*)d_in[4];
    const float* batt = (const float*)d_in[5];
    float* out = (float*)d_out;

    int n = in_sizes[0] / D;
    int E = in_sizes[1] / 2;
    int nb = (n + 1023) / 1024;
    int e4 = (E + 3) / 4;

    // side stream + events for fork/join inside graph capture (created once)
    static cudaStream_t s1 = nullptr;
    static cudaEvent_t ev_fork = nullptr, ev_join = nullptr;
    if (s1 == nullptr) {
        cudaStreamCreateWithFlags(&s1, cudaStreamNonBlocking);
        cudaEventCreateWithFlags(&ev_fork, cudaEventDisableTiming);
        cudaEventCreateWithFlags(&ev_join, cudaEventDisableTiming);
    }

    // fork: FULL edge pipeline (hist -> scans -> sort) concurrent with GEMM
    cudaEventRecord(ev_fork, 0);
    cudaStreamWaitEvent(s1, ev_fork, 0);
    hist_kernel<<<(e4 + 255) / 256, 256, 0, s1>>>(ei, E);
    scan1_kernel<<<nb, 1024, 0, s1>>>(n);
    scan2_kernel<<<1, NB_MAX, 0, s1>>>(nb);
    sort_kernel<<<(E + 255) / 256, 256, 0, s1>>>(ei, E);
    cudaEventRecord(ev_join, s1);

    gemm_kernel<<<(n + 127) / 128, 256>>>(x, W, b, Watt, n);

    cudaStreamWaitEvent(0, ev_join, 0);
    aggregate_kernel<<<((long long)n * 32 + 255) / 256, 256>>>(out, batt, n, E);
}